// round 1
// baseline (speedup 1.0000x reference)
#include <cuda_runtime.h>
#include <cuda_bf16.h>
#include <cstddef>

// hungarian_matcher cost kernel
// out[b, q, j] = 5 * sum_d |pred_boxes[b,q,d] - target_boxes[b*per+j, d]|
//              - softmax(pred_logits[b,q,:])[target_ids[b*per+j]]
//
// Shapes (fixed by the dataset, re-derived on host from in_sizes for safety):
//   pred_logits  (16, 900, 4)  f32
//   pred_boxes   (16, 900, 11) f32
//   target_boxes (1024, 11)    f32
//   target_ids   (1024,)       i32
//   out          (16, 900, 64) f32

namespace {

constexpr int BOX = 11;   // box_dim
constexpr int NC  = 4;    // n_classes
constexpr int PER = 64;   // targets per batch
constexpr int QT  = 4;    // queries per block (900 % 4 == 0)

__global__ __launch_bounds__(PER * QT)
void matcher_kernel(const float* __restrict__ logits,
                    const float* __restrict__ boxes,
                    const float* __restrict__ tboxes,
                    const int*   __restrict__ tids,
                    float* __restrict__ out,
                    int nq)
{
    const int b  = blockIdx.y;
    const int q0 = blockIdx.x * QT;
    const int j  = threadIdx.x;   // target index within batch, 0..63
    const int qy = threadIdx.y;   // query within tile, 0..QT-1
    const int q  = q0 + qy;

    __shared__ float s_pb[QT][BOX + 1];   // pred boxes, padded row
    __shared__ float s_negprob[QT][NC];   // -softmax per query

    // Cooperative load of QT*BOX pred-box floats
    const int ltid = qy * PER + j;
    for (int i = ltid; i < QT * BOX; i += QT * PER) {
        const int yy = i / BOX, dd = i % BOX;
        const int qq = q0 + yy;
        s_pb[yy][dd] = (qq < nq) ? boxes[((size_t)b * nq + qq) * BOX + dd] : 0.0f;
    }

    // One thread per query computes the (negated) softmax row
    if (j == 0 && q < nq) {
        const float* lp = logits + ((size_t)b * nq + q) * NC;
        float l[NC];
        float m = -1e30f;
#pragma unroll
        for (int c = 0; c < NC; c++) { l[c] = lp[c]; m = fmaxf(m, l[c]); }
        float s = 0.0f;
#pragma unroll
        for (int c = 0; c < NC; c++) { l[c] = __expf(l[c] - m); s += l[c]; }
        const float inv = __frcp_rn(s);
#pragma unroll
        for (int c = 0; c < NC; c++) s_negprob[qy][c] = -l[c] * inv;
    }

    // This thread's target box -> registers (shared across all qy via L1)
    float tb[BOX];
    const float* tp = tboxes + ((size_t)b * PER + j) * BOX;
#pragma unroll
    for (int d = 0; d < BOX; d++) tb[d] = tp[d];
    const int cls = tids[b * PER + j];

    __syncthreads();

    if (q >= nq) return;

    // L1 distance: s_pb reads are warp-uniform broadcasts (conflict-free)
    float s = 0.0f;
#pragma unroll
    for (int d = 0; d < BOX; d++) s += fabsf(s_pb[qy][d] - tb[d]);

    const float cost = fmaf(5.0f, s, s_negprob[qy][cls]);

    // threadIdx.x contiguous in memory -> fully coalesced store
    out[((size_t)b * nq + q) * PER + j] = cost;
}

} // namespace

extern "C" void kernel_launch(void* const* d_in, const int* in_sizes, int n_in,
                              void* d_out, int out_size)
{
    const float* logits = (const float*)d_in[0];
    const float* boxes  = (const float*)d_in[1];
    const float* tboxes = (const float*)d_in[2];
    const int*   tids   = (const int*)d_in[3];
    float* out = (float*)d_out;

    // Derive shapes on host (no device reads; graph-capture safe).
    const int n_total = in_sizes[3];                 // 1024
    const int box_dim = in_sizes[2] / n_total;       // 11
    const int bsnq    = in_sizes[1] / box_dim;       // 14400
    const int per     = out_size / bsnq;             // 64
    const int bs      = n_total / per;               // 16
    const int nq      = bsnq / bs;                   // 900

    (void)n_in; (void)box_dim;

    dim3 block(PER, QT);
    dim3 grid((nq + QT - 1) / QT, bs);
    matcher_kernel<<<grid, block>>>(logits, boxes, tboxes, tids, out, nq);
}

// round 2
// speedup vs baseline: 1.4883x; 1.4883x over previous
#include <cuda_runtime.h>
#include <cuda_bf16.h>
#include <cstddef>

// hungarian_matcher cost kernel
// out[b, q, j] = 5 * sum_d |pred_boxes[b,q,d] - target_boxes[b*64+j, d]|
//              - softmax(pred_logits[b,q,:])[target_ids[b*64+j]]
//
// Shapes: pred_logits (16,900,4) f32, pred_boxes (16,900,11) f32,
//         target_boxes (1024,11) f32, target_ids (1024,) i32,
//         out (16,900,64) f32.
//
// Layout: grid (45, 16) = 720 CTAs (single wave on 148 SMs at occ>=5).
// Block 256 = 64 j-lanes x 4 qy. Each thread keeps its target box in
// registers and produces 5 query rows (QT=20 queries per CTA, 45*20=900).

namespace {

constexpr int BOX = 11;
constexpr int NC  = 4;
constexpr int PER = 64;
constexpr int QT  = 20;   // queries per CTA
constexpr int QPT = 5;    // queries per thread (QT / blockDim.y)

__global__ __launch_bounds__(PER * 4)
void matcher_kernel(const float* __restrict__ logits,
                    const float* __restrict__ boxes,
                    const float* __restrict__ tboxes,
                    const int*   __restrict__ tids,
                    float* __restrict__ out,
                    int nq)
{
    const int b  = blockIdx.y;
    const int q0 = blockIdx.x * QT;
    const int j  = threadIdx.x;           // target lane 0..63
    const int qy = threadIdx.y;           // 0..3
    const int t  = qy * PER + j;          // linear tid 0..255

    __shared__ float s_tb[PER * BOX];          // 704 floats: target boxes of batch b
    __shared__ float s_pb[QT * BOX];           // 220 floats: pred boxes of this tile
    __shared__ float s_negprob[QT * NC];       // 80 floats: -softmax rows

    // --- Stage target boxes (704 floats = 176 float4, coalesced) ---
    {
        const float4* src = (const float4*)(tboxes + (size_t)b * PER * BOX);
        float4* dst = (float4*)s_tb;
        if (t < PER * BOX / 4) dst[t] = src[t];   // 176 < 256: one shot
    }

    // --- Stage pred boxes for QT queries (220 floats, coalesced) ---
    if (t < QT * BOX) {
        s_pb[t] = boxes[((size_t)b * nq + q0) * BOX + t];
    }

    // --- Softmax rows: thread t < QT handles query q0+t ---
    if (t < QT) {
        const float* lp = logits + ((size_t)b * nq + q0 + t) * NC;
        float l[NC];
        float m = -1e30f;
#pragma unroll
        for (int c = 0; c < NC; c++) { l[c] = lp[c]; m = fmaxf(m, l[c]); }
        float s = 0.0f;
#pragma unroll
        for (int c = 0; c < NC; c++) { l[c] = __expf(l[c] - m); s += l[c]; }
        const float inv = __frcp_rn(s);
#pragma unroll
        for (int c = 0; c < NC; c++) s_negprob[t * NC + c] = -l[c] * inv;
    }

    // This thread's class id (one cached LDG; warp-coalesced across j)
    const int cls = tids[b * PER + j];

    __syncthreads();

    // --- Target box to registers (stride-11 LDS: gcd(11,32)=1, conflict-free) ---
    float tb[BOX];
#pragma unroll
    for (int d = 0; d < BOX; d++) tb[d] = s_tb[j * BOX + d];

    // --- 5 query rows per thread; pred-box LDS are warp-uniform broadcasts ---
    float* orow = out + ((size_t)b * nq + q0 + qy * QPT) * PER + j;
#pragma unroll
    for (int k = 0; k < QPT; k++) {
        const int ql = qy * QPT + k;
        float s = 0.0f;
#pragma unroll
        for (int d = 0; d < BOX; d++) s += fabsf(s_pb[ql * BOX + d] - tb[d]);
        orow[(size_t)k * PER] = fmaf(5.0f, s, s_negprob[ql * NC + cls]);
    }
}

} // namespace

extern "C" void kernel_launch(void* const* d_in, const int* in_sizes, int n_in,
                              void* d_out, int out_size)
{
    const float* logits = (const float*)d_in[0];
    const float* boxes  = (const float*)d_in[1];
    const float* tboxes = (const float*)d_in[2];
    const int*   tids   = (const int*)d_in[3];
    float* out = (float*)d_out;

    const int n_total = in_sizes[3];                 // 1024
    const int box_dim = in_sizes[2] / n_total;       // 11
    const int bsnq    = in_sizes[1] / box_dim;       // 14400
    const int per     = out_size / bsnq;             // 64
    const int bs      = n_total / per;               // 16
    const int nq      = bsnq / bs;                   // 900

    (void)n_in; (void)box_dim; (void)per;

    dim3 block(PER, 4);
    dim3 grid(nq / QT, bs);                          // 45 x 16 = 720
    matcher_kernel<<<grid, block>>>(logits, boxes, tboxes, tids, out, nq);
}